// round 16
// baseline (speedup 1.0000x reference)
#include <cuda_runtime.h>
#include <cstdint>

// Depthwise 3D conv 3x3x3, SAME, stride 1.
// x: (4,16,112,112,64) f32 NDHWC; w: (3,3,3,1,64) f32.
//
// R16 = R13 body (HPT=3: thread = 2 channels x 8 w x 3 h-rows; 5-row window,
// 10-deep LDG bursts, full 9-tap kd plane in registers; -18% l1tex traffic
// vs the HPT=2 variants) with __launch_bounds__(64,11): cap 93 regs squeezes
// the 96-reg natural demand by 3 (addressing rematerialization expected, not
// spills) and lifts blocks/SM 10 -> 11 (20 -> 22 warps). R13 measured L1=56%
// at occ 27.5% — latency-starved, so +10% warps should convert directly.

#define N_  4
#define D_  16
#define H_  112
#define W_  112
#define C_  64
#define WPT 8
#define HPT 3
#define CS  (C_ / 2)   // 32 ull per spatial position
#define ROWSTEP (W_ * CS)

typedef unsigned long long ull;

__device__ __forceinline__ ull ffma2(ull a, ull b, ull c) {
    ull d;
    asm("fma.rn.f32x2 %0, %1, %2, %3;" : "=l"(d) : "l"(a), "l"(b), "l"(c));
    return d;
}

template <bool INT>
__device__ __forceinline__ void conv_body(
    const ull* __restrict__ xp, const ull* __restrict__ swp,
    ull* __restrict__ out, int n, int d, int h0, int w0, int tx) {

    const bool wlo = INT || (w0 > 0);
    const bool whi = INT || (w0 + WPT < W_);

    ull acc[HPT][WPT];
#pragma unroll
    for (int j = 0; j < HPT; j++)
#pragma unroll
        for (int i = 0; i < WPT; i++) acc[j][i] = 0ull;

#pragma unroll
    for (int kd = 0; kd < 3; kd++) {
        const int zd = d + kd - 1;
        if (!INT && (unsigned)zd >= D_) continue;

        // full 9-tap plane for this kd (channel pair tx), loaded once
        ull wt[3][3];
#pragma unroll
        for (int kh = 0; kh < 3; kh++)
#pragma unroll
            for (int kw = 0; kw < 3; kw++)
                wt[kh][kw] = swp[((kd * 3 + kh) * 3 + kw) * CS + tx];

        // pointer to (n, zd, h0-1, w0, tx); advances one h-row per r
        const ull* rowp =
            xp + ((((n * D_ + zd) * H_ + (h0 - 1)) * W_ + w0) * CS + tx);

#pragma unroll
        for (int r = 0; r < HPT + 2; r++) {    // zh = h0-1 .. h0+3
            const int zh = h0 - 1 + r;
            const bool rowOk = INT || ((unsigned)zh < H_);

            if (rowOk) {
                // batched 10-LDG row preload, immediate offsets
                ull rv[WPT + 2];
                rv[0] = wlo ? rowp[-CS] : 0ull;
#pragma unroll
                for (int q = 0; q < WPT; q++)
                    rv[q + 1] = rowp[q * CS];
                rv[WPT + 1] = whi ? rowp[WPT * CS] : 0ull;

                // row r feeds outputs j with kh = r-j, 0 <= r-j <= 2
#pragma unroll
                for (int j = 0; j < HPT; j++) {
                    if (j <= r && r <= j + 2) {
                        const int kh = r - j;
#pragma unroll
                        for (int i = 0; i < WPT; i++) {
                            acc[j][i] = ffma2(rv[i],     wt[kh][0], acc[j][i]);
                            acc[j][i] = ffma2(rv[i + 1], wt[kh][1], acc[j][i]);
                            acc[j][i] = ffma2(rv[i + 2], wt[kh][2], acc[j][i]);
                        }
                    }
                }
            }
            rowp += ROWSTEP;
        }
    }

    ull* __restrict__ op =
        out + ((((n * D_ + d) * H_ + h0) * W_ + w0) * CS + tx);
#pragma unroll
    for (int j = 0; j < HPT; j++) {
        if (INT || (unsigned)(h0 + j) < H_) {
#pragma unroll
            for (int i = 0; i < WPT; i++)
                op[(j * W_ + i) * CS] = acc[j][i];
        }
    }
}

__global__ void __launch_bounds__(64, 11)
dwconv3d_kernel(const float* __restrict__ x,
                const float* __restrict__ wgt,
                float* __restrict__ out) {
    const ull* __restrict__ swp = reinterpret_cast<const ull*>(wgt);
    const ull* __restrict__ xp  = reinterpret_cast<const ull*>(x);
    ull* __restrict__ op        = reinterpret_cast<ull*>(out);

    const int tx = threadIdx.x;                        // channel pair 0..31
    const int h0 = blockIdx.y * 6 + threadIdx.y * 3;   // 0,3,...,111
    const int w0 = blockIdx.x * WPT;                   // 0..104
    const int nd = blockIdx.z;
    const int n  = nd >> 4;
    const int d  = nd & 15;

    // Block-uniform interior: rows by*6-1 .. by*6+7 all in [0,111],
    // plus no d/w halo clamping anywhere in the block.
    const bool interior =
        (d >= 1) && (d <= 14) &&
        (blockIdx.y >= 1) && (blockIdx.y <= 17) &&
        (blockIdx.x >= 1) && (blockIdx.x <= (W_ / WPT) - 2);

    if (interior)
        conv_body<true>(xp, swp, op, n, d, h0, w0, tx);
    else
        conv_body<false>(xp, swp, op, n, d, h0, w0, tx);
}

extern "C" void kernel_launch(void* const* d_in, const int* in_sizes, int n_in,
                              void* d_out, int out_size) {
    const float* x = (const float*)d_in[0];
    const float* w = (const float*)d_in[1];
    float* o = (float*)d_out;

    dim3 block(32, 2, 1);                        // 64 threads
    // grid.y = ceil(112 / 6) = 19 (last row-block guarded in edge path)
    dim3 grid(W_ / WPT, (H_ + 5) / 6, N_ * D_);  // 14 x 19 x 64
    dwconv3d_kernel<<<grid, block>>>(x, w, o);
}

// round 17
// speedup vs baseline: 1.6816x; 1.6816x over previous
#include <cuda_runtime.h>
#include <cstdint>

// Depthwise 3D conv 3x3x3, SAME, stride 1.
// x: (4,16,112,112,64) f32 NDHWC; w: (3,3,3,1,64) f32.
//
// FINAL (R12 config — best measured: 86.78us wall / 85.25us ncu, 78 regs,
// no spills). Thread: 2 channels (f32x2 packed FMA), 8 w-outputs, 2 h-rows.
// Interior blocks (~70%): guard-free double-buffered row pipeline — row r+1's
// 10-LDG burst issues before row r's 48 packed FMAs. Edge blocks: guarded
// single-buffer body. Weights via direct LDG (L1-resident, no smem).
// __launch_bounds__(64, 11): cap 93 >= 78 natural demand (R7/R16 lesson:
// never cap below natural demand — the allocator spills, not trims).

#define N_  4
#define D_  16
#define H_  112
#define W_  112
#define C_  64
#define WPT 8
#define CS  (C_ / 2)   // 32 ull per spatial position
#define ROWSTEP (W_ * CS)

typedef unsigned long long ull;

__device__ __forceinline__ ull ffma2(ull a, ull b, ull c) {
    ull d;
    asm("fma.rn.f32x2 %0, %1, %2, %3;" : "=l"(d) : "l"(a), "l"(b), "l"(c));
    return d;
}

// ---------------- interior: guard-free, double-buffered row pipeline --------
__device__ __forceinline__ void conv_interior(
    const ull* __restrict__ xp, const ull* __restrict__ swp,
    ull* __restrict__ out, int n, int d, int h0, int w0, int tx) {

    ull acc0[WPT], acc1[WPT];
#pragma unroll
    for (int i = 0; i < WPT; i++) { acc0[i] = 0ull; acc1[i] = 0ull; }

#pragma unroll
    for (int kd = 0; kd < 3; kd++) {
        const int zd = d + kd - 1;                    // always in [0,15]
        const ull* rowp =
            xp + ((((n * D_ + zd) * H_ + (h0 - 1)) * W_ + w0) * CS + tx);

        ull wa0 = 0, wa1 = 0, wa2 = 0;
        ull wb0, wb1, wb2;

        ull buf[2][WPT + 2];

        // prime: row r=0 (zh = h0-1), 10 unconditional LDGs
#pragma unroll
        for (int j = 0; j < WPT + 2; j++)
            buf[0][j] = rowp[(j - 1) * CS];

#pragma unroll
        for (int r = 0; r < 4; r++) {                 // zh = h0-1+r
            // prefetch next row into the other buffer BEFORE this row's FMAs
            if (r < 3) {
                const ull* np = rowp + ROWSTEP;
#pragma unroll
                for (int j = 0; j < WPT + 2; j++)
                    buf[(r + 1) & 1][j] = np[(j - 1) * CS];
            }

            // weight rotate + fetch (drains under prefetch latency)
            wb0 = wa0; wb1 = wa1; wb2 = wa2;
            if (r < 3) {
                const int base = (kd * 9 + r * 3) * CS + tx;
                wa0 = swp[base];
                wa1 = swp[base + CS];
                wa2 = swp[base + 2 * CS];
            }

            const ull* rv = buf[r & 1];
#pragma unroll
            for (int i = 0; i < WPT; i++) {
                if (r <= 2) {                          // output h0, kh=r
                    acc0[i] = ffma2(rv[i],     wa0, acc0[i]);
                    acc0[i] = ffma2(rv[i + 1], wa1, acc0[i]);
                    acc0[i] = ffma2(rv[i + 2], wa2, acc0[i]);
                }
                if (r >= 1) {                          // output h0+1, kh=r-1
                    acc1[i] = ffma2(rv[i],     wb0, acc1[i]);
                    acc1[i] = ffma2(rv[i + 1], wb1, acc1[i]);
                    acc1[i] = ffma2(rv[i + 2], wb2, acc1[i]);
                }
            }
            rowp += ROWSTEP;
        }
    }

    ull* __restrict__ op =
        out + ((((n * D_ + d) * H_ + h0) * W_ + w0) * CS + tx);
#pragma unroll
    for (int i = 0; i < WPT; i++) {
        op[i * CS] = acc0[i];
        op[ROWSTEP + i * CS] = acc1[i];
    }
}

// ---------------- edge: guarded single-buffer ------------------------------
__device__ __forceinline__ void conv_edge(
    const ull* __restrict__ xp, const ull* __restrict__ swp,
    ull* __restrict__ out, int n, int d, int h0, int w0, int tx) {

    const bool wlo = (w0 > 0);
    const bool whi = (w0 + WPT < W_);

    ull acc0[WPT], acc1[WPT];
#pragma unroll
    for (int i = 0; i < WPT; i++) { acc0[i] = 0ull; acc1[i] = 0ull; }

#pragma unroll
    for (int kd = 0; kd < 3; kd++) {
        const int zd = d + kd - 1;
        if ((unsigned)zd >= D_) continue;

        const ull* rowp =
            xp + ((((n * D_ + zd) * H_ + (h0 - 1)) * W_ + w0) * CS + tx);

        ull wa0 = 0, wa1 = 0, wa2 = 0;
        ull wb0, wb1, wb2;

#pragma unroll
        for (int r = 0; r < 4; r++) {
            const int zh = h0 - 1 + r;
            const bool rowOk = ((unsigned)zh < H_);

            ull rv[WPT + 2];
            if (rowOk) {
                rv[0] = wlo ? rowp[-CS] : 0ull;
#pragma unroll
                for (int j = 0; j < WPT; j++)
                    rv[j + 1] = rowp[j * CS];
                rv[WPT + 1] = whi ? rowp[WPT * CS] : 0ull;
            }

            wb0 = wa0; wb1 = wa1; wb2 = wa2;
            if (r < 3) {
                const int base = (kd * 9 + r * 3) * CS + tx;
                wa0 = swp[base];
                wa1 = swp[base + CS];
                wa2 = swp[base + 2 * CS];
            }

            if (rowOk) {
#pragma unroll
                for (int i = 0; i < WPT; i++) {
                    if (r <= 2) {
                        acc0[i] = ffma2(rv[i],     wa0, acc0[i]);
                        acc0[i] = ffma2(rv[i + 1], wa1, acc0[i]);
                        acc0[i] = ffma2(rv[i + 2], wa2, acc0[i]);
                    }
                    if (r >= 1) {
                        acc1[i] = ffma2(rv[i],     wb0, acc1[i]);
                        acc1[i] = ffma2(rv[i + 1], wb1, acc1[i]);
                        acc1[i] = ffma2(rv[i + 2], wb2, acc1[i]);
                    }
                }
            }
            rowp += ROWSTEP;
        }
    }

    ull* __restrict__ op =
        out + ((((n * D_ + d) * H_ + h0) * W_ + w0) * CS + tx);
#pragma unroll
    for (int i = 0; i < WPT; i++) {
        op[i * CS] = acc0[i];
        op[ROWSTEP + i * CS] = acc1[i];
    }
}

__global__ void __launch_bounds__(64, 11)
dwconv3d_kernel(const float* __restrict__ x,
                const float* __restrict__ wgt,
                float* __restrict__ out) {
    const ull* __restrict__ swp = reinterpret_cast<const ull*>(wgt);
    const ull* __restrict__ xp  = reinterpret_cast<const ull*>(x);
    ull* __restrict__ op        = reinterpret_cast<ull*>(out);

    const int tx = threadIdx.x;                       // channel pair 0..31
    const int h0 = blockIdx.y * 4 + threadIdx.y * 2;  // even rows 0..110
    const int w0 = blockIdx.x * WPT;                  // 0..104
    const int nd = blockIdx.z;
    const int n  = nd >> 4;
    const int d  = nd & 15;

    const bool interior =
        (d >= 1) && (d <= 14) &&
        (blockIdx.y >= 1) && (blockIdx.y <= (H_ / 4) - 2) &&
        (blockIdx.x >= 1) && (blockIdx.x <= (W_ / WPT) - 2);

    if (interior)
        conv_interior(xp, swp, op, n, d, h0, w0, tx);
    else
        conv_edge(xp, swp, op, n, d, h0, w0, tx);
}

extern "C" void kernel_launch(void* const* d_in, const int* in_sizes, int n_in,
                              void* d_out, int out_size) {
    const float* x = (const float*)d_in[0];
    const float* w = (const float*)d_in[1];
    float* o = (float*)d_out;

    dim3 block(32, 2, 1);                        // 64 threads
    dim3 grid(W_ / WPT, H_ / 4, N_ * D_);        // 14 x 28 x 64
    dwconv3d_kernel<<<grid, block>>>(x, w, o);
}